// round 10
// baseline (speedup 1.0000x reference)
#include <cuda_runtime.h>
#include <cstdint>

#define LGRID  512
#define BATCH  32768
#define NCH    32
#define NCHUNK (LGRID / NCH)         // 16
#define TPB    256

typedef unsigned long long ull;

#define FMA2(d, a, b, c) asm("fma.rn.f32x2 %0, %1, %2, %3;" : "=l"(d) : "l"(a), "l"(b), "l"(c))
#define MUL2(d, a, b)    asm("mul.rn.f32x2 %0, %1, %2;"     : "=l"(d) : "l"(a), "l"(b))
#define ADD2(d, a, b)    asm("add.rn.f32x2 %0, %1, %2;"     : "=l"(d) : "l"(a), "l"(b))

__device__ __forceinline__ ull pack2(float lo, float hi) {
    ull r;
    asm("mov.b64 %0, {%1, %2};" : "=l"(r) : "f"(lo), "f"(hi));
    return r;
}

// per-step packed prefix coefficients: [n][m], m = S,Q,P,R,U,V,W
__device__ __align__(16) ull g_cf[LGRID][7];

// ------------- kernel 1: 1-CTA warp-shuffle scan of the 7 prefix scalars -------------
__device__ __forceinline__ void excl_scan3(float v0, float v1, float v2,
                                           float& o0, float& o1, float& o2,
                                           float* ws) {
    const int lane = threadIdx.x & 31;
    const int wid  = threadIdx.x >> 5;

    float i0 = v0, i1 = v1, i2 = v2;
    #pragma unroll
    for (int d = 1; d < 32; d <<= 1) {
        const float t0 = __shfl_up_sync(0xffffffffu, i0, d);
        const float t1 = __shfl_up_sync(0xffffffffu, i1, d);
        const float t2 = __shfl_up_sync(0xffffffffu, i2, d);
        if (lane >= d) { i0 += t0; i1 += t1; i2 += t2; }
    }
    if (lane == 31) { ws[wid] = i0; ws[16 + wid] = i1; ws[32 + wid] = i2; }
    __syncthreads();
    if (wid == 0 && lane < 16) {
        float s0 = ws[lane], s1 = ws[16 + lane], s2 = ws[32 + lane];
        #pragma unroll
        for (int d = 1; d < 16; d <<= 1) {
            const float t0 = __shfl_up_sync(0xffffu, s0, d);
            const float t1 = __shfl_up_sync(0xffffu, s1, d);
            const float t2 = __shfl_up_sync(0xffffu, s2, d);
            if (lane >= d) { s0 += t0; s1 += t1; s2 += t2; }
        }
        ws[lane] = s0; ws[16 + lane] = s1; ws[32 + lane] = s2;
    }
    __syncthreads();
    const float f0 = (wid > 0) ? ws[wid - 1]      : 0.0f;
    const float f1 = (wid > 0) ? ws[16 + wid - 1] : 0.0f;
    const float f2 = (wid > 0) ? ws[32 + wid - 1] : 0.0f;
    o0 = f0 + i0 - v0;
    o1 = f1 + i1 - v1;
    o2 = f2 + i2 - v2;
    __syncthreads();
}

__global__ __launch_bounds__(512)
void scan_kernel(const float* __restrict__ s_grid) {
    __shared__ float ws[48];
    const int n = threadIdx.x;

    const float s0v = __ldg(s_grid);
    const float sv  = __ldg(s_grid + n);
    const float S   = sv - s0v;
    const float h   = (n < LGRID - 1) ? (__ldg(s_grid + n + 1) - sv) : 0.0f;

    float Q, R, P, V, W, U, d1, d2;
    excl_scan3(h * S, h * S * S, 0.0f, Q, R, d1, ws);
    excl_scan3(h * Q, h * R, h * S * Q, P, V, W, ws);
    excl_scan3(h * P, 0.0f, 0.0f, U, d1, d2, ws);

    g_cf[n][0] = pack2(S, S);
    g_cf[n][1] = pack2(Q, Q);
    g_cf[n][2] = pack2(P, P);
    g_cf[n][3] = pack2(R, R);
    g_cf[n][4] = pack2(U, U);
    g_cf[n][5] = pack2(V, V);
    g_cf[n][6] = pack2(W, W);
}

// ------------- kernel 2: fused gvec + output evaluation -------------
struct V4 { float a, t, n, c; };

__global__ __launch_bounds__(TPB, 4)
void taylor_kernel(const float* __restrict__ s_grid,
                   const float* __restrict__ y0,
                   const float* __restrict__ w,
                   float* __restrict__ out) {
    __shared__ float sG[7][4][256];     // 28 KB: Taylor vectors for this CTA's 256 trajectories
    __shared__ ull   sh_h[NCH];

    const int tid   = threadIdx.x;
    const int chunk = blockIdx.x >> 7;     // 128 CTAs per chunk
    const int cw    = blockIdx.x & 127;
    const int n0    = chunk * NCH;

    // packed (h,h) table for this chunk (last slot padded 0)
    if (tid < NCH) {
        const float h = (n0 + tid + 1 < LGRID)
                      ? (__ldg(s_grid + n0 + tid + 1) - __ldg(s_grid + n0 + tid))
                      : 0.0f;
        sh_h[tid] = pack2(h, h);
    }

    // ---- prologue: per-thread gvec for one trajectory ----
    {
        const int b = cw * 256 + tid;

        const float A = y0[0 * BATCH + b];
        const float T = y0[1 * BATCH + b];
        const float N = y0[2 * BATCH + b];
        const float C = y0[3 * BATCH + b];

        const float w0_  = __ldg(w + 0),  w1_  = __ldg(w + 1),  w2_  = __ldg(w + 2);
        const float w3_  = __ldg(w + 3),  w4_  = __ldg(w + 4),  w5_  = __ldg(w + 5);
        const float w6_  = __ldg(w + 6),  w7_  = __ldg(w + 7),  w8_  = __ldg(w + 8);
        const float w9_  = __ldg(w + 9),  w10_ = __ldg(w + 10), w11_ = __ldg(w + 11);
        const float w12_ = __ldg(w + 12), w13_ = __ldg(w + 13), w14_ = __ldg(w + 14);
        const float w15_ = __ldg(w + 15), w16_ = __ldg(w + 16), w17_ = __ldg(w + 17);
        const float w18_ = __ldg(w + 18), w19_ = __ldg(w + 19), w20_ = __ldg(w + 20);

        V4 f0;
        f0.a = fmaf(w2_, A * A, fmaf(w1_, A, w0_));
        f0.t = fmaf(w5_, T * T, fmaf(w4_, T, w3_)) + fmaf(w8_, A * T, fmaf(w7_, A * A, w6_ * A));
        f0.n = fmaf(w11_, N * N, fmaf(w10_, N, w9_)) + fmaf(w14_, T * N, fmaf(w13_, T * T, w12_ * T));
        f0.c = fmaf(w17_, C * C, fmaf(w16_, C, w15_)) + fmaf(w20_, N * C, fmaf(w19_, N * N, w18_ * N));

        const float jAA = fmaf(2.0f * w2_, A, w1_);
        const float jTA = fmaf(2.0f * w7_, A, fmaf(w8_, T, w6_));
        const float jTT = fmaf(2.0f * w5_, T, fmaf(w8_, A, w4_));
        const float jNT = fmaf(2.0f * w13_, T, fmaf(w14_, N, w12_));
        const float jNN = fmaf(2.0f * w11_, N, fmaf(w14_, T, w10_));
        const float jCN = fmaf(2.0f * w19_, N, fmaf(w20_, C, w18_));
        const float jCC = fmaf(2.0f * w17_, C, fmaf(w20_, N, w16_));

        auto applyJ = [&](const V4& v) {
            V4 r;
            r.a = jAA * v.a;
            r.t = fmaf(jTA, v.a, jTT * v.t);
            r.n = fmaf(jNT, v.t, jNN * v.n);
            r.c = fmaf(jCN, v.n, jCC * v.c);
            return r;
        };
        auto applyH = [&](const V4& u, const V4& v) {
            V4 r;
            r.a = 2.0f * w2_ * u.a * v.a;
            r.t = 2.0f * w5_ * u.t * v.t + 2.0f * w7_ * u.a * v.a + w8_ * (u.a * v.t + u.t * v.a);
            r.n = 2.0f * w11_ * u.n * v.n + 2.0f * w13_ * u.t * v.t + w14_ * (u.t * v.n + u.n * v.t);
            r.c = 2.0f * w17_ * u.c * v.c + 2.0f * w19_ * u.n * v.n + w20_ * (u.n * v.c + u.c * v.n);
            return r;
        };

        const V4 g2  = applyJ(f0);
        const V4 g3a = applyJ(g2);
        V4 h00 = applyH(f0, f0);
        h00.a *= 0.5f; h00.t *= 0.5f; h00.n *= 0.5f; h00.c *= 0.5f;
        const V4 g4a = applyJ(g3a);
        const V4 g4b = applyJ(h00);
        const V4 g4c = applyH(f0, g2);

        const V4 G[7] = { f0, g2, g3a, h00, g4a, g4b, g4c };
        #pragma unroll
        for (int m = 0; m < 7; ++m) {
            sG[m][0][tid] = G[m].a;
            sG[m][1][tid] = G[m].t;
            sG[m][2][tid] = G[m].n;
            sG[m][3][tid] = G[m].c;
        }
    }
    __syncthreads();

    // ---- gather component-split slices into registers ----
    const int lane = tid & 31;
    const int wid  = tid >> 5;
    const int c    = lane >> 3;
    const int q    = lane & 7;
    const int tw   = cw * 8 + wid;
    const int j0   = tw * 32 + q * 4;         // global trajectory base
    const int jl   = wid * 32 + q * 4;        // CTA-local trajectory base

    ull Glo[7], Ghi[7];
    #pragma unroll
    for (int m = 0; m < 7; ++m) {
        const float4 g4 = *(const float4*)&sG[m][c][jl];
        Glo[m] = pack2(g4.x, g4.y);
        Ghi[m] = pack2(g4.z, g4.w);
    }

    const float4 yv = *(const float4*)(y0 + (size_t)c * BATCH + j0);
    const ull ylo = pack2(yv.x, yv.y);
    const ull yhi = pack2(yv.z, yv.w);

    // coefficient registers at chunk start (from scan kernel)
    ull S = g_cf[n0][0], Q = g_cf[n0][1], P = g_cf[n0][2], R = g_cf[n0][3];
    ull U = g_cf[n0][4], V = g_cf[n0][5], W = g_cf[n0][6];

    float* base = out + (size_t)n0 * (4 * BATCH) + (size_t)c * BATCH + j0;

    #pragma unroll 4
    for (int i = 0; i < NCH; ++i) {
        ull olo = ylo, ohi = yhi;
        FMA2(olo, S, Glo[0], olo);  FMA2(ohi, S, Ghi[0], ohi);
        FMA2(olo, Q, Glo[1], olo);  FMA2(ohi, Q, Ghi[1], ohi);
        FMA2(olo, P, Glo[2], olo);  FMA2(ohi, P, Ghi[2], ohi);
        FMA2(olo, R, Glo[3], olo);  FMA2(ohi, R, Ghi[3], ohi);
        FMA2(olo, U, Glo[4], olo);  FMA2(ohi, U, Ghi[4], ohi);
        FMA2(olo, V, Glo[5], olo);  FMA2(ohi, V, Ghi[5], ohi);
        FMA2(olo, W, Glo[6], olo);  FMA2(ohi, W, Ghi[6], ohi);

        asm volatile("st.global.cs.v2.u64 [%0], {%1, %2};"
                     :: "l"(base), "l"(olo), "l"(ohi) : "memory");

        // advance coefficients n -> n+1 (all reads use pre-update values)
        const ull H = sh_h[i];
        ull t;
        MUL2(t, H, S);
        FMA2(U, H, P, U);
        FMA2(V, H, R, V);
        FMA2(P, H, Q, P);
        FMA2(W, t, Q, W);
        FMA2(R, t, S, R);
        ADD2(Q, Q, t);
        ADD2(S, S, H);

        base += 4 * BATCH;
    }
}

extern "C" void kernel_launch(void* const* d_in, const int* in_sizes, int n_in,
                              void* d_out, int out_size) {
    const float* s_grid = (const float*)d_in[0];
    const float* y0     = (const float*)d_in[1];
    const float* w      = (const float*)d_in[2];
    float* out          = (float*)d_out;

    scan_kernel<<<1, 512>>>(s_grid);
    taylor_kernel<<<NCHUNK * 128, TPB>>>(s_grid, y0, w, out);
}